// round 5
// baseline (speedup 1.0000x reference)
#include <cuda_runtime.h>
#include <cuda_bf16.h>
#include <mma.h>
#include <math.h>

using namespace nvcuda;

#define TT   2048
#define DD   768
#define HH   12
#define DKK  64
#define FFD  2048
#define LL   12
#define VV   50304
#define KC   4
#define EPSF 1e-6f

// weight plane offsets (elements)
#define W4      589824      // 768*768
#define WFF     1572864     // 768*2048
#define OFF_WQ  0
#define OFF_WK  7077888
#define OFF_WV  14155776
#define OFF_WO  21233664
#define OFF_WG  28311552
#define OFF_WU  47185920
#define OFF_WD  66060288
#define OFF_LM  84934656
#define TOT_W   123568128

// ---------------- scratch ----------------
__device__ float g_h   [TT*DD];
__device__ float g_x   [TT*DD];
__device__ float g_q   [TT*DD];
__device__ float g_k   [TT*DD];
__device__ float g_v   [TT*DD];
__device__ float g_qc  [TT*DD];
__device__ float g_kc  [TT*DD];
__device__ float g_vc  [TT*DD];
__device__ float g_o   [TT*DD];
__device__ float g_beta[TT*HH];
__device__ float g_gate[TT*FFD];
__device__ float g_up  [TT*FFD];
__device__ float g_rowloss[TT];

__device__ __nv_bfloat16 g_whi[TOT_W];
__device__ __nv_bfloat16 g_wlo[TOT_W];
__device__ __nv_bfloat16 g_xhi[TT*DD],  g_xlo[TT*DD];
__device__ __nv_bfloat16 g_ohi[TT*DD],  g_olo[TT*DD];
__device__ __nv_bfloat16 g_ghi[TT*FFD], g_glo[TT*FFD];

// ---------------- helpers ----------------
__device__ __forceinline__ void split2(float v, __nv_bfloat16& hi, __nv_bfloat16& lo) {
    hi = __float2bfloat16(v);
    lo = __float2bfloat16(v - __bfloat162float(hi));
}

// fp32 -> bf16 hi/lo planes, vectorized
__global__ void cvt_k(const float* __restrict__ src, __nv_bfloat16* __restrict__ hi,
                      __nv_bfloat16* __restrict__ lo, int n4) {
    int i = blockIdx.x * 256 + threadIdx.x;
    if (i >= n4) return;
    float4 v = ((const float4*)src)[i];
    __nv_bfloat16 h0, h1, h2, h3, l0, l1, l2, l3;
    split2(v.x, h0, l0); split2(v.y, h1, l1); split2(v.z, h2, l2); split2(v.w, h3, l3);
    ((__nv_bfloat162*)hi)[2*i]   = __nv_bfloat162(h0, h1);
    ((__nv_bfloat162*)hi)[2*i+1] = __nv_bfloat162(h2, h3);
    ((__nv_bfloat162*)lo)[2*i]   = __nv_bfloat162(l0, l1);
    ((__nv_bfloat162*)lo)[2*i+1] = __nv_bfloat162(l2, l3);
}

__global__ void embed_k(const int* __restrict__ idx, const float* __restrict__ emb,
                        float* __restrict__ h) {
    int i = blockIdx.x * 256 + threadIdx.x;
    if (i < TT * DD) {
        int t = i / DD, d = i - t * DD;
        h[i] = emb[(size_t)idx[t] * DD + d];
    }
}

// rmsnorm; writes fp32 + bf16 hi/lo planes
__global__ void rmsnorm_k(const float* __restrict__ in, const float* __restrict__ w,
                          float* __restrict__ out,
                          __nv_bfloat16* __restrict__ ohi, __nv_bfloat16* __restrict__ olo) {
    int t = blockIdx.x;
    const float* row = in + (size_t)t * DD;
    __shared__ float red[256];
    float s = 0.f;
    for (int i = threadIdx.x; i < DD; i += 256) { float v = row[i]; s += v * v; }
    red[threadIdx.x] = s; __syncthreads();
    for (int off = 128; off > 0; off >>= 1) {
        if (threadIdx.x < off) red[threadIdx.x] += red[threadIdx.x + off];
        __syncthreads();
    }
    float scale = rsqrtf(red[0] / (float)DD + EPSF);
    for (int i = threadIdx.x; i < DD; i += 256) {
        float v = row[i] * scale * w[i];
        size_t o = (size_t)t * DD + i;
        if (out) out[o] = v;
        __nv_bfloat16 hi, lo; split2(v, hi, lo);
        ohi[o] = hi; olo[o] = lo;
    }
}

// ---------------- bf16 hi/lo tensor-core GEMM (3-MMA split) ----------------
// C[M,N] (+)= (Ahi+Alo)(Bhi+Blo) dropping Alo*Blo.  BM=128 BN=128 BK=32, 256 thr.
// Register double buffer: load next k-tile to regs while MMAs run.
// grid: x = M/128 (so L2 keeps B slice across m-blocks), y = N/128, z selects fused op.
#define LDAe 40
#define LDBe 136

template <bool ACC>
__global__ __launch_bounds__(256, 1) void gemm_bf(
    const __nv_bfloat16* __restrict__ Ah, const __nv_bfloat16* __restrict__ Al,
    const __nv_bfloat16* __restrict__ Bh0, const __nv_bfloat16* __restrict__ Bh1, const __nv_bfloat16* __restrict__ Bh2,
    const __nv_bfloat16* __restrict__ Bl0, const __nv_bfloat16* __restrict__ Bl1, const __nv_bfloat16* __restrict__ Bl2,
    float* __restrict__ C0, float* __restrict__ C1, float* __restrict__ C2,
    int M, int N, int K) {
    const __nv_bfloat16* Bh = (blockIdx.z == 0) ? Bh0 : (blockIdx.z == 1) ? Bh1 : Bh2;
    const __nv_bfloat16* Bl = (blockIdx.z == 0) ? Bl0 : (blockIdx.z == 1) ? Bl1 : Bl2;
    float*               C  = (blockIdx.z == 0) ? C0  : (blockIdx.z == 1) ? C1  : C2;

    __shared__ __nv_bfloat16 sAh[128 * LDAe];
    __shared__ __nv_bfloat16 sAl[128 * LDAe];
    __shared__ __nv_bfloat16 sBh[32 * LDBe];
    __shared__ __nv_bfloat16 sBl[32 * LDBe];

    const int bm = blockIdx.x * 128;
    const int bn = blockIdx.y * 128;
    const int tid = threadIdx.x;
    const int warp = tid >> 5;
    const int wm = warp >> 2;
    const int wn = warp & 3;

    const int row_a = tid >> 1, colA = (tid & 1) * 16;
    const int row_b = tid >> 3, colB = (tid & 7) * 16;

    const __nv_bfloat16* pAh = Ah + (size_t)(bm + row_a) * K + colA;
    const __nv_bfloat16* pAl = Al + (size_t)(bm + row_a) * K + colA;
    const __nv_bfloat16* pBh = Bh + (size_t)row_b * N + bn + colB;
    const __nv_bfloat16* pBl = Bl + (size_t)row_b * N + bn + colB;

    wmma::fragment<wmma::accumulator, 16, 16, 16, float> acc[4][2];
#pragma unroll
    for (int mi = 0; mi < 4; mi++)
#pragma unroll
        for (int ni = 0; ni < 2; ni++) wmma::fill_fragment(acc[mi][ni], 0.f);

    uint4 rah0, rah1, ral0, ral1, rbh0, rbh1, rbl0, rbl1;
    rah0 = *(const uint4*)(pAh);          rah1 = *(const uint4*)(pAh + 8);
    ral0 = *(const uint4*)(pAl);          ral1 = *(const uint4*)(pAl + 8);
    rbh0 = *(const uint4*)(pBh);          rbh1 = *(const uint4*)(pBh + 8);
    rbl0 = *(const uint4*)(pBl);          rbl1 = *(const uint4*)(pBl + 8);

    for (int k0 = 0; k0 < K; k0 += 32) {
        *(uint4*)&sAh[row_a * LDAe + colA]     = rah0;
        *(uint4*)&sAh[row_a * LDAe + colA + 8] = rah1;
        *(uint4*)&sAl[row_a * LDAe + colA]     = ral0;
        *(uint4*)&sAl[row_a * LDAe + colA + 8] = ral1;
        *(uint4*)&sBh[row_b * LDBe + colB]     = rbh0;
        *(uint4*)&sBh[row_b * LDBe + colB + 8] = rbh1;
        *(uint4*)&sBl[row_b * LDBe + colB]     = rbl0;
        *(uint4*)&sBl[row_b * LDBe + colB + 8] = rbl1;
        __syncthreads();

        if (k0 + 32 < K) {
            const __nv_bfloat16* a_h = pAh + k0 + 32;
            const __nv_bfloat16* a_l = pAl + k0 + 32;
            const __nv_bfloat16* b_h = pBh + (size_t)(k0 + 32) * N;
            const __nv_bfloat16* b_l = pBl + (size_t)(k0 + 32) * N;
            rah0 = *(const uint4*)(a_h); rah1 = *(const uint4*)(a_h + 8);
            ral0 = *(const uint4*)(a_l); ral1 = *(const uint4*)(a_l + 8);
            rbh0 = *(const uint4*)(b_h); rbh1 = *(const uint4*)(b_h + 8);
            rbl0 = *(const uint4*)(b_l); rbl1 = *(const uint4*)(b_l + 8);
        }

#pragma unroll
        for (int kk = 0; kk < 32; kk += 16) {
            wmma::fragment<wmma::matrix_a, 16, 16, 16, __nv_bfloat16, wmma::row_major> ah[4], al[4];
#pragma unroll
            for (int mi = 0; mi < 4; mi++) {
                wmma::load_matrix_sync(ah[mi], &sAh[(wm * 64 + mi * 16) * LDAe + kk], LDAe);
                wmma::load_matrix_sync(al[mi], &sAl[(wm * 64 + mi * 16) * LDAe + kk], LDAe);
            }
#pragma unroll
            for (int ni = 0; ni < 2; ni++) {
                wmma::fragment<wmma::matrix_b, 16, 16, 16, __nv_bfloat16, wmma::row_major> bh, bl;
                wmma::load_matrix_sync(bh, &sBh[kk * LDBe + wn * 32 + ni * 16], LDBe);
                wmma::load_matrix_sync(bl, &sBl[kk * LDBe + wn * 32 + ni * 16], LDBe);
#pragma unroll
                for (int mi = 0; mi < 4; mi++) {
                    wmma::mma_sync(acc[mi][ni], ah[mi], bh, acc[mi][ni]);
                    wmma::mma_sync(acc[mi][ni], al[mi], bh, acc[mi][ni]);
                    wmma::mma_sync(acc[mi][ni], ah[mi], bl, acc[mi][ni]);
                }
            }
        }
        __syncthreads();
    }

#pragma unroll
    for (int mi = 0; mi < 4; mi++)
#pragma unroll
        for (int ni = 0; ni < 2; ni++) {
            float* cp = C + (size_t)(bm + wm * 64 + mi * 16) * N + bn + wn * 32 + ni * 16;
            if (ACC) {
                wmma::fragment<wmma::accumulator, 16, 16, 16, float> cf;
                wmma::load_matrix_sync(cf, cp, N, wmma::mem_row_major);
#pragma unroll
                for (int e = 0; e < cf.num_elements; e++) acc[mi][ni].x[e] += cf.x[e];
            }
            wmma::store_matrix_sync(cp, acc[mi][ni], N, wmma::mem_row_major);
        }
}

// beta: warp per (t,h)
__global__ void beta_k(const float* __restrict__ x, const float* __restrict__ Wb,
                       float* __restrict__ beta) {
    int g = blockIdx.x * 8 + (threadIdx.x >> 5);
    int lane = threadIdx.x & 31;
    if (g >= TT * HH) return;
    int t = g / HH, h = g - t * HH;
    const float* xr = x + (size_t)t * DD;
    float s = 0.f;
#pragma unroll
    for (int i = 0; i < DD / 32; i++) s += xr[lane + i * 32] * Wb[(lane + i * 32) * HH + h];
#pragma unroll
    for (int off = 16; off > 0; off >>= 1) s += __shfl_xor_sync(0xffffffffu, s, off);
    if (lane == 0) beta[g] = 1.f / (1.f + expf(-s));
}

// fused causal conv+SiLU for q,k,v (z selects)
__global__ void conv_silu_k(const float* __restrict__ x0, const float* __restrict__ x1,
                            const float* __restrict__ x2,
                            const float* __restrict__ w0, const float* __restrict__ w1,
                            const float* __restrict__ w2,
                            float* __restrict__ y0, float* __restrict__ y1,
                            float* __restrict__ y2) {
    const float* x = (blockIdx.y == 0) ? x0 : (blockIdx.y == 1) ? x1 : x2;
    const float* w = (blockIdx.y == 0) ? w0 : (blockIdx.y == 1) ? w1 : w2;
    float*       y = (blockIdx.y == 0) ? y0 : (blockIdx.y == 1) ? y1 : y2;
    int i = blockIdx.x * 256 + threadIdx.x;
    if (i >= TT * DD) return;
    int t = i / DD, d = i - t * DD;
    float acc = 0.f;
#pragma unroll
    for (int j = 0; j < KC; j++) {
        int tt = t - (KC - 1) + j;
        if (tt >= 0) acc += x[(size_t)tt * DD + d] * w[d * KC + j];
    }
    y[i] = acc / (1.f + expf(-acc));
}

// l2norm for q and k in one launch (z selects)
__global__ void l2norm_k(float* __restrict__ a, float* __restrict__ b) {
    float* x = (blockIdx.y == 0) ? a : b;
    int g = blockIdx.x * blockDim.x + threadIdx.x;
    if (g >= TT * HH) return;
    int t = g / HH, h = g - t * HH;
    float* p = x + (size_t)t * DD + h * DKK;
    float s = 0.f;
#pragma unroll
    for (int i = 0; i < DKK; i++) s += p[i] * p[i];
    float sc = rsqrtf(s + EPSF);
#pragma unroll
    for (int i = 0; i < DKK; i++) p[i] *= sc;
}

// per-head RMSNorm, writes bf16 hi/lo
__global__ void headnorm_k(const float* __restrict__ o, const float* __restrict__ w,
                           __nv_bfloat16* __restrict__ ohi, __nv_bfloat16* __restrict__ olo) {
    int g = blockIdx.x * blockDim.x + threadIdx.x;
    if (g >= TT * HH) return;
    int t = g / HH, h = g - t * HH;
    const float* p = o + (size_t)t * DD + h * DKK;
    float s = 0.f;
#pragma unroll
    for (int i = 0; i < DKK; i++) s += p[i] * p[i];
    float sc = rsqrtf(s / (float)DKK + EPSF);
#pragma unroll
    for (int i = 0; i < DKK; i++) {
        float v = p[i] * sc * w[i];
        __nv_bfloat16 hi, lo; split2(v, hi, lo);
        size_t idx = (size_t)t * DD + h * DKK + i;
        ohi[idx] = hi; olo[idx] = lo;
    }
}

// delta-rule: block per head, 128 threads (2-way i-split), float4 smem reads
__global__ void delta_k(const float* __restrict__ q, const float* __restrict__ k,
                        const float* __restrict__ v, const float* __restrict__ beta,
                        float* __restrict__ o) {
    const int h = blockIdx.x;
    const int tid = threadIdx.x;
    const int half = tid >> 6;
    const int j = tid & 63;
    float S[32];
#pragma unroll
    for (int i = 0; i < 32; i++) S[i] = 0.f;
    __shared__ float qs[DKK], ks[DKK], vs[DKK];
    __shared__ float pk[2][DKK], po[2][DKK];
    __shared__ float bsh;

    float qn = 0.f, kn = 0.f, vn = 0.f, bn_ = 0.f;
    if (tid < 64) {
        int b0 = h * DKK + j;
        qn = q[b0]; kn = k[b0]; vn = v[b0];
        bn_ = beta[h];
    }
    const int i0 = half * 32;
    for (int t = 0; t < TT; t++) {
        if (tid < 64) {
            qs[j] = qn; ks[j] = kn; vs[j] = vn;
            if (j == 0) bsh = bn_;
        }
        __syncthreads();
        if (tid < 64 && t + 1 < TT) {
            int nb = (t + 1) * DD + h * DKK + j;
            qn = q[nb]; kn = k[nb]; vn = v[nb];
            bn_ = beta[(t + 1) * HH + h];
        }
        float d = 0.f;
#pragma unroll
        for (int i = 0; i < 32; i += 4) {
            float4 k4 = *(const float4*)&ks[i0 + i];
            d += k4.x * S[i] + k4.y * S[i + 1] + k4.z * S[i + 2] + k4.w * S[i + 3];
        }
        pk[half][j] = d;
        __syncthreads();
        float w = bsh * (vs[j] - (pk[0][j] + pk[1][j]));
        float od = 0.f;
#pragma unroll
        for (int i = 0; i < 32; i += 4) {
            float4 k4 = *(const float4*)&ks[i0 + i];
            float4 q4 = *(const float4*)&qs[i0 + i];
            S[i]     += k4.x * w; od += q4.x * S[i];
            S[i + 1] += k4.y * w; od += q4.y * S[i + 1];
            S[i + 2] += k4.z * w; od += q4.z * S[i + 2];
            S[i + 3] += k4.w * w; od += q4.w * S[i + 3];
        }
        po[half][j] = od;
        __syncthreads();
        if (tid < 64) o[t * DD + h * DKK + j] = po[0][j] + po[1][j];
    }
}

// g = silu(g) * u, writes bf16 hi/lo
__global__ void silu_mul_k(const float* __restrict__ g, const float* __restrict__ u,
                           __nv_bfloat16* __restrict__ ghi, __nv_bfloat16* __restrict__ glo) {
    int i = blockIdx.x * 256 + threadIdx.x;
    if (i < TT * FFD) {
        float x = g[i];
        float r = (x / (1.f + expf(-x))) * u[i];
        __nv_bfloat16 hi, lo; split2(r, hi, lo);
        ghi[i] = hi; glo[i] = lo;
    }
}

__global__ void loss_rows_k(const float* __restrict__ logits, const int* __restrict__ tgt,
                            float* __restrict__ rowloss) {
    int t = blockIdx.x;
    const float* row = logits + (size_t)t * VV;
    __shared__ float red[256];
    float m = -1e30f;
    for (int i = threadIdx.x; i < VV; i += 256) m = fmaxf(m, row[i]);
    red[threadIdx.x] = m; __syncthreads();
    for (int off = 128; off > 0; off >>= 1) {
        if (threadIdx.x < off) red[threadIdx.x] = fmaxf(red[threadIdx.x], red[threadIdx.x + off]);
        __syncthreads();
    }
    m = red[0]; __syncthreads();
    float s = 0.f;
    for (int i = threadIdx.x; i < VV; i += 256) s += expf(row[i] - m);
    red[threadIdx.x] = s; __syncthreads();
    for (int off = 128; off > 0; off >>= 1) {
        if (threadIdx.x < off) red[threadIdx.x] += red[threadIdx.x + off];
        __syncthreads();
    }
    if (threadIdx.x == 0) {
        int tg = tgt[t];
        if (tg < 0) tg = 0;
        if (tg > VV - 1) tg = VV - 1;
        rowloss[t] = (m + logf(red[0])) - row[tg];
    }
}

__global__ void loss_final_k(const float* __restrict__ rowloss, float* __restrict__ out) {
    __shared__ float red[256];
    float s = 0.f;
    for (int i = threadIdx.x; i < TT; i += 256) s += rowloss[i];
    red[threadIdx.x] = s; __syncthreads();
    for (int off = 128; off > 0; off >>= 1) {
        if (threadIdx.x < off) red[threadIdx.x] += red[threadIdx.x + off];
        __syncthreads();
    }
    if (threadIdx.x == 0) out[0] = red[0] / (float)TT;
}

// ---------------- host launch ----------------

extern "C" void kernel_launch(void* const* d_in, const int* in_sizes, int n_in,
                              void* d_out, int out_size) {
    const int*   idx          = (const int*)d_in[0];
    const int*   targets      = (const int*)d_in[1];
    const float* embed        = (const float*)d_in[2];
    const float* Wq           = (const float*)d_in[3];
    const float* Wk           = (const float*)d_in[4];
    const float* Wv           = (const float*)d_in[5];
    const float* conv_q       = (const float*)d_in[6];
    const float* conv_k       = (const float*)d_in[7];
    const float* conv_v       = (const float*)d_in[8];
    const float* Wb           = (const float*)d_in[9];
    const float* o_norm_w     = (const float*)d_in[10];
    const float* Wo           = (const float*)d_in[11];
    const float* attn_norm_w  = (const float*)d_in[12];
    const float* mlp_norm_w   = (const float*)d_in[13];
    const float* Wgate        = (const float*)d_in[14];
    const float* Wup          = (const float*)d_in[15];
    const float* Wdown        = (const float*)d_in[16];
    const float* final_norm_w = (const float*)d_in[17];
    const float* lm_head      = (const float*)d_in[18];
    float* out = (float*)d_out;

    float *h, *x, *q, *k, *v, *qc, *kc, *vc, *o, *bet, *gate, *up, *rowloss;
    cudaGetSymbolAddress((void**)&h,   g_h);
    cudaGetSymbolAddress((void**)&x,   g_x);
    cudaGetSymbolAddress((void**)&q,   g_q);
    cudaGetSymbolAddress((void**)&k,   g_k);
    cudaGetSymbolAddress((void**)&v,   g_v);
    cudaGetSymbolAddress((void**)&qc,  g_qc);
    cudaGetSymbolAddress((void**)&kc,  g_kc);
    cudaGetSymbolAddress((void**)&vc,  g_vc);
    cudaGetSymbolAddress((void**)&o,   g_o);
    cudaGetSymbolAddress((void**)&bet, g_beta);
    cudaGetSymbolAddress((void**)&gate,g_gate);
    cudaGetSymbolAddress((void**)&up,  g_up);
    cudaGetSymbolAddress((void**)&rowloss, g_rowloss);

    __nv_bfloat16 *whi, *wlo, *xhi, *xlo, *ohi, *olo, *ghi, *glo;
    cudaGetSymbolAddress((void**)&whi, g_whi);
    cudaGetSymbolAddress((void**)&wlo, g_wlo);
    cudaGetSymbolAddress((void**)&xhi, g_xhi);
    cudaGetSymbolAddress((void**)&xlo, g_xlo);
    cudaGetSymbolAddress((void**)&ohi, g_ohi);
    cudaGetSymbolAddress((void**)&olo, g_olo);
    cudaGetSymbolAddress((void**)&ghi, g_ghi);
    cudaGetSymbolAddress((void**)&glo, g_glo);

    // --- pre-convert all weights to bf16 hi/lo planes ---
    {
        struct { const float* src; size_t off; int n; } segs[8] = {
            {Wq,     OFF_WQ, LL * W4},
            {Wk,     OFF_WK, LL * W4},
            {Wv,     OFF_WV, LL * W4},
            {Wo,     OFF_WO, LL * W4},
            {Wgate,  OFF_WG, LL * WFF},
            {Wup,    OFF_WU, LL * WFF},
            {Wdown,  OFF_WD, LL * WFF},
            {lm_head,OFF_LM, DD * VV},
        };
        for (int s = 0; s < 8; s++) {
            int n4 = segs[s].n / 4;
            cvt_k<<<(n4 + 255) / 256, 256>>>(segs[s].src, whi + segs[s].off, wlo + segs[s].off, n4);
        }
    }

    const int eltTD = (TT * DD + 255) / 256;
    const int eltTH = (TT * HH + 255) / 256;
    const int eltTF = (TT * FFD + 255) / 256;

    embed_k<<<eltTD, 256>>>(idx, embed, h);

    dim3 g_qkv(TT / 128, DD / 128, 3);
    dim3 g_one(TT / 128, DD / 128, 1);
    dim3 g_gu (TT / 128, FFD / 128, 2);
    dim3 g_vcb(TT / 128, VV / 128, 1);
    dim3 g_conv(eltTD, 3);
    dim3 g_l2(eltTH, 2);

    for (int l = 0; l < LL; l++) {
        rmsnorm_k<<<TT, 256>>>(h, attn_norm_w + (size_t)l * DD, x, xhi, xlo);

        gemm_bf<false><<<g_qkv, 256>>>(xhi, xlo,
            whi + OFF_WQ + (size_t)l * W4, whi + OFF_WK + (size_t)l * W4, whi + OFF_WV + (size_t)l * W4,
            wlo + OFF_WQ + (size_t)l * W4, wlo + OFF_WK + (size_t)l * W4, wlo + OFF_WV + (size_t)l * W4,
            q, k, v, TT, DD, DD);
        beta_k<<<(TT * HH + 7) / 8, 256>>>(x, Wb + (size_t)l * DD * HH, bet);

        conv_silu_k<<<g_conv, 256>>>(q, k, v,
            conv_q + (size_t)l * DD * KC, conv_k + (size_t)l * DD * KC, conv_v + (size_t)l * DD * KC,
            qc, kc, vc);
        l2norm_k<<<g_l2, 256>>>(qc, kc);

        delta_k<<<HH, 128>>>(qc, kc, vc, bet, o);
        headnorm_k<<<eltTH, 256>>>(o, o_norm_w + (size_t)l * DKK, ohi, olo);

        gemm_bf<true><<<g_one, 256>>>(ohi, olo,
            whi + OFF_WO + (size_t)l * W4, nullptr, nullptr,
            wlo + OFF_WO + (size_t)l * W4, nullptr, nullptr,
            h, nullptr, nullptr, TT, DD, DD);

        rmsnorm_k<<<TT, 256>>>(h, mlp_norm_w + (size_t)l * DD, x, xhi, xlo);
        gemm_bf<false><<<g_gu, 256>>>(xhi, xlo,
            whi + OFF_WG + (size_t)l * WFF, whi + OFF_WU + (size_t)l * WFF, nullptr,
            wlo + OFF_WG + (size_t)l * WFF, wlo + OFF_WU + (size_t)l * WFF, nullptr,
            gate, up, nullptr, TT, FFD, DD);
        silu_mul_k<<<eltTF, 256>>>(gate, up, ghi, glo);
        gemm_bf<true><<<g_one, 256>>>(ghi, glo,
            whi + OFF_WD + (size_t)l * WFF, nullptr, nullptr,
            wlo + OFF_WD + (size_t)l * WFF, nullptr, nullptr,
            h, nullptr, nullptr, TT, DD, FFD);
    }

    rmsnorm_k<<<TT, 256>>>(h, final_norm_w, nullptr, xhi, xlo);

    if ((long long)out_size >= (long long)TT * VV) {
        gemm_bf<false><<<g_vcb, 256>>>(xhi, xlo,
            whi + OFF_LM, nullptr, nullptr,
            wlo + OFF_LM, nullptr, nullptr,
            out, nullptr, nullptr, TT, VV, DD);
        loss_rows_k<<<TT, 256>>>(out, targets, rowloss);
        if ((long long)out_size > (long long)TT * VV)
            loss_final_k<<<1, 256>>>(rowloss, out + (size_t)TT * VV);
    }
}

// round 8
// speedup vs baseline: 1.2937x; 1.2937x over previous
#include <cuda_runtime.h>
#include <cuda_bf16.h>
#include <mma.h>
#include <math.h>
#include <stdint.h>

using namespace nvcuda;

#define TT   2048
#define DD   768
#define HH   12
#define DKK  64
#define FFD  2048
#define LL   12
#define VV   50304
#define KC   4
#define EPSF 1e-6f

// weight plane offsets (elements), [K,N] layout
#define W4      589824
#define WFF     1572864
#define OFF_WQ  0
#define OFF_WK  7077888
#define OFF_WV  14155776
#define OFF_WO  21233664
#define OFF_WG  28311552
#define OFF_WU  47185920
#define OFF_WD  66060288
#define OFF_LM  84934656
#define TOT_W   123568128

// ---------------- scratch ----------------
__device__ float g_h   [TT*DD];
__device__ float g_x   [TT*DD];
__device__ float g_q   [TT*DD];
__device__ float g_k   [TT*DD];
__device__ float g_v   [TT*DD];
__device__ float g_qc  [TT*DD];
__device__ float g_kc  [TT*DD];
__device__ float g_vc  [TT*DD];
__device__ float g_o   [TT*DD];
__device__ float g_beta[TT*HH];
__device__ float g_gate[TT*FFD];
__device__ float g_up  [TT*FFD];
__device__ float g_rowloss[TT];

__device__ __nv_bfloat16 g_whi[TOT_W];
__device__ __nv_bfloat16 g_wlo[TOT_W];
__device__ __nv_bfloat16 g_xhi[TT*DD],  g_xlo[TT*DD];
__device__ __nv_bfloat16 g_ohi[TT*DD],  g_olo[TT*DD];
__device__ __nv_bfloat16 g_ghi[TT*FFD], g_glo[TT*FFD];

// ---------------- helpers ----------------
__device__ __forceinline__ void split2(float v, __nv_bfloat16& hi, __nv_bfloat16& lo) {
    hi = __float2bfloat16(v);
    lo = __float2bfloat16(v - __bfloat162float(hi));
}
__device__ __forceinline__ uint32_t smem_u32(const void* p) {
    uint32_t a;
    asm("{ .reg .u64 t; cvta.to.shared.u64 t, %1; cvt.u32.u64 %0, t; }" : "=r"(a) : "l"(p));
    return a;
}
__device__ __forceinline__ void cpa16(uint32_t dst, const void* src) {
    asm volatile("cp.async.cg.shared.global [%0], [%1], 16;" :: "r"(dst), "l"(src));
}
__device__ __forceinline__ void cpa_commit() { asm volatile("cp.async.commit_group;" ::: "memory"); }
template <int NN> __device__ __forceinline__ void cpa_wait() {
    asm volatile("cp.async.wait_group %0;" :: "n"(NN) : "memory");
}

// fp32 -> bf16 hi/lo planes
__global__ void cvt_k(const float* __restrict__ src, __nv_bfloat16* __restrict__ hi,
                      __nv_bfloat16* __restrict__ lo, int n4) {
    int i = blockIdx.x * 256 + threadIdx.x;
    if (i >= n4) return;
    float4 v = ((const float4*)src)[i];
    __nv_bfloat16 h0, h1, h2, h3, l0, l1, l2, l3;
    split2(v.x, h0, l0); split2(v.y, h1, l1); split2(v.z, h2, l2); split2(v.w, h3, l3);
    ((__nv_bfloat162*)hi)[2*i]   = __nv_bfloat162(h0, h1);
    ((__nv_bfloat162*)hi)[2*i+1] = __nv_bfloat162(h2, h3);
    ((__nv_bfloat162*)lo)[2*i]   = __nv_bfloat162(l0, l1);
    ((__nv_bfloat162*)lo)[2*i+1] = __nv_bfloat162(l2, l3);
}

__global__ void embed_k(const int* __restrict__ idx, const float* __restrict__ emb,
                        float* __restrict__ h) {
    int i = blockIdx.x * 256 + threadIdx.x;
    if (i < TT * DD) {
        int t = i / DD, d = i - t * DD;
        h[i] = emb[(size_t)idx[t] * DD + d];
    }
}

__global__ void rmsnorm_k(const float* __restrict__ in, const float* __restrict__ w,
                          float* __restrict__ out,
                          __nv_bfloat16* __restrict__ ohi, __nv_bfloat16* __restrict__ olo) {
    int t = blockIdx.x;
    const float* row = in + (size_t)t * DD;
    __shared__ float red[256];
    float s = 0.f;
    for (int i = threadIdx.x; i < DD; i += 256) { float v = row[i]; s += v * v; }
    red[threadIdx.x] = s; __syncthreads();
    for (int off = 128; off > 0; off >>= 1) {
        if (threadIdx.x < off) red[threadIdx.x] += red[threadIdx.x + off];
        __syncthreads();
    }
    float scale = rsqrtf(red[0] / (float)DD + EPSF);
    for (int i = threadIdx.x; i < DD; i += 256) {
        float v = row[i] * scale * w[i];
        size_t o = (size_t)t * DD + i;
        if (out) out[o] = v;
        __nv_bfloat16 hi, lo; split2(v, hi, lo);
        ohi[o] = hi; olo[o] = lo;
    }
}

// ---------------- cp.async double-buffered split-bf16 GEMM ----------------
// C[M,N] (+)= (Ahi+Alo)(Bhi+Blo) dropping Alo*Blo. BM=128 BN=128 BK=32, 256 thr.
// grid.x = M/128 (L2 keeps B slice), grid.y = N/128, grid.z = fused op select.
#define LDAe 40     // elems per A smem row (32 used), 80B (16B-mult)
#define LDBe 136    // elems per B smem row (128 used), 272B (16B-mult)
#define A_PL (128 * LDAe * 2)          // 10240 B per plane
#define B_PL (32 * LDBe * 2)           // 8704 B per plane
#define ST_AH 0
#define ST_AL (A_PL)
#define ST_BH (2 * A_PL)
#define ST_BL (2 * A_PL + B_PL)
#define STAGE_B (2 * A_PL + 2 * B_PL)  // 37888 B
#define SMEM_GEMM (2 * STAGE_B)        // 75776 B

template <bool ACC>
__global__ __launch_bounds__(256, 1) void gemm_bf(
    const __nv_bfloat16* __restrict__ Ah, const __nv_bfloat16* __restrict__ Al,
    const __nv_bfloat16* __restrict__ Bh0, const __nv_bfloat16* __restrict__ Bh1, const __nv_bfloat16* __restrict__ Bh2,
    const __nv_bfloat16* __restrict__ Bl0, const __nv_bfloat16* __restrict__ Bl1, const __nv_bfloat16* __restrict__ Bl2,
    float* __restrict__ C0, float* __restrict__ C1, float* __restrict__ C2,
    int M, int N, int K) {
    extern __shared__ char smem[];
    const __nv_bfloat16* Bh = (blockIdx.z == 0) ? Bh0 : (blockIdx.z == 1) ? Bh1 : Bh2;
    const __nv_bfloat16* Bl = (blockIdx.z == 0) ? Bl0 : (blockIdx.z == 1) ? Bl1 : Bl2;
    float*               C  = (blockIdx.z == 0) ? C0  : (blockIdx.z == 1) ? C1  : C2;

    const int bm = blockIdx.x * 128;
    const int bn = blockIdx.y * 128;
    const int tid = threadIdx.x;
    const int warp = tid >> 5;
    const int wm = warp >> 2;
    const int wn = warp & 3;

    const uint32_t sb = smem_u32(smem);

    // A copy mapping: row tid>>1, col chunk (tid&1)*16 (+0,+8)
    const int rowA = tid >> 1, ca = (tid & 1) * 16;
    // B copy mapping: row tid>>3, col chunk (tid&7)*16 (+0,+8)
    const int rowB = tid >> 3, cb = (tid & 7) * 16;

    const __nv_bfloat16* gAh = Ah + (size_t)(bm + rowA) * K + ca;
    const __nv_bfloat16* gAl = Al + (size_t)(bm + rowA) * K + ca;
    const __nv_bfloat16* gBh = Bh + (size_t)rowB * N + bn + cb;
    const __nv_bfloat16* gBl = Bl + (size_t)rowB * N + bn + cb;

    const uint32_t dAoff = (uint32_t)(rowA * LDAe + ca) * 2;
    const uint32_t dBoff = (uint32_t)(rowB * LDBe + cb) * 2;

    wmma::fragment<wmma::accumulator, 16, 16, 16, float> acc[4][2];
#pragma unroll
    for (int mi = 0; mi < 4; mi++)
#pragma unroll
        for (int ni = 0; ni < 2; ni++) wmma::fill_fragment(acc[mi][ni], 0.f);

    auto issue = [&](int s, int k0) {
        uint32_t base = sb + s * STAGE_B;
        cpa16(base + ST_AH + dAoff,      gAh + k0);
        cpa16(base + ST_AH + dAoff + 16, gAh + k0 + 8);
        cpa16(base + ST_AL + dAoff,      gAl + k0);
        cpa16(base + ST_AL + dAoff + 16, gAl + k0 + 8);
        cpa16(base + ST_BH + dBoff,      gBh + (size_t)k0 * N);
        cpa16(base + ST_BH + dBoff + 16, gBh + (size_t)k0 * N + 8);
        cpa16(base + ST_BL + dBoff,      gBl + (size_t)k0 * N);
        cpa16(base + ST_BL + dBoff + 16, gBl + (size_t)k0 * N + 8);
        cpa_commit();
    };

    const int KT = K / 32;
    issue(0, 0);

    for (int kt = 0; kt < KT; kt++) {
        if (kt + 1 < KT) {
            issue((kt + 1) & 1, (kt + 1) * 32);
            cpa_wait<1>();
        } else {
            cpa_wait<0>();
        }
        __syncthreads();

        const int s = kt & 1;
        const __nv_bfloat16* pAh = (const __nv_bfloat16*)(smem + s * STAGE_B + ST_AH);
        const __nv_bfloat16* pAl = (const __nv_bfloat16*)(smem + s * STAGE_B + ST_AL);
        const __nv_bfloat16* pBh = (const __nv_bfloat16*)(smem + s * STAGE_B + ST_BH);
        const __nv_bfloat16* pBl = (const __nv_bfloat16*)(smem + s * STAGE_B + ST_BL);

#pragma unroll
        for (int kk = 0; kk < 32; kk += 16) {
            wmma::fragment<wmma::matrix_a, 16, 16, 16, __nv_bfloat16, wmma::row_major> ah[4], al[4];
#pragma unroll
            for (int mi = 0; mi < 4; mi++) {
                wmma::load_matrix_sync(ah[mi], pAh + (wm * 64 + mi * 16) * LDAe + kk, LDAe);
                wmma::load_matrix_sync(al[mi], pAl + (wm * 64 + mi * 16) * LDAe + kk, LDAe);
            }
#pragma unroll
            for (int ni = 0; ni < 2; ni++) {
                wmma::fragment<wmma::matrix_b, 16, 16, 16, __nv_bfloat16, wmma::row_major> bh, bl;
                wmma::load_matrix_sync(bh, pBh + kk * LDBe + wn * 32 + ni * 16, LDBe);
                wmma::load_matrix_sync(bl, pBl + kk * LDBe + wn * 32 + ni * 16, LDBe);
#pragma unroll
                for (int mi = 0; mi < 4; mi++) {
                    wmma::mma_sync(acc[mi][ni], ah[mi], bh, acc[mi][ni]);
                    wmma::mma_sync(acc[mi][ni], al[mi], bh, acc[mi][ni]);
                    wmma::mma_sync(acc[mi][ni], ah[mi], bl, acc[mi][ni]);
                }
            }
        }
        __syncthreads();
    }

#pragma unroll
    for (int mi = 0; mi < 4; mi++)
#pragma unroll
        for (int ni = 0; ni < 2; ni++) {
            float* cp = C + (size_t)(bm + wm * 64 + mi * 16) * N + bn + wn * 32 + ni * 16;
            if (ACC) {
                wmma::fragment<wmma::accumulator, 16, 16, 16, float> cf;
                wmma::load_matrix_sync(cf, cp, N, wmma::mem_row_major);
#pragma unroll
                for (int e = 0; e < cf.num_elements; e++) acc[mi][ni].x[e] += cf.x[e];
            }
            wmma::store_matrix_sync(cp, acc[mi][ni], N, wmma::mem_row_major);
        }
}

// beta: warp per (t,h)
__global__ void beta_k(const float* __restrict__ x, const float* __restrict__ Wb,
                       float* __restrict__ beta) {
    int g = blockIdx.x * 8 + (threadIdx.x >> 5);
    int lane = threadIdx.x & 31;
    if (g >= TT * HH) return;
    int t = g / HH, h = g - t * HH;
    const float* xr = x + (size_t)t * DD;
    float s = 0.f;
#pragma unroll
    for (int i = 0; i < DD / 32; i++) s += xr[lane + i * 32] * Wb[(lane + i * 32) * HH + h];
#pragma unroll
    for (int off = 16; off > 0; off >>= 1) s += __shfl_xor_sync(0xffffffffu, s, off);
    if (lane == 0) beta[g] = 1.f / (1.f + expf(-s));
}

__global__ void conv_silu_k(const float* __restrict__ x0, const float* __restrict__ x1,
                            const float* __restrict__ x2,
                            const float* __restrict__ w0, const float* __restrict__ w1,
                            const float* __restrict__ w2,
                            float* __restrict__ y0, float* __restrict__ y1,
                            float* __restrict__ y2) {
    const float* x = (blockIdx.y == 0) ? x0 : (blockIdx.y == 1) ? x1 : x2;
    const float* w = (blockIdx.y == 0) ? w0 : (blockIdx.y == 1) ? w1 : w2;
    float*       y = (blockIdx.y == 0) ? y0 : (blockIdx.y == 1) ? y1 : y2;
    int i = blockIdx.x * 256 + threadIdx.x;
    if (i >= TT * DD) return;
    int t = i / DD, d = i - t * DD;
    float acc = 0.f;
#pragma unroll
    for (int j = 0; j < KC; j++) {
        int tt = t - (KC - 1) + j;
        if (tt >= 0) acc += x[(size_t)tt * DD + d] * w[d * KC + j];
    }
    y[i] = acc / (1.f + expf(-acc));
}

__global__ void l2norm_k(float* __restrict__ a, float* __restrict__ b) {
    float* x = (blockIdx.y == 0) ? a : b;
    int g = blockIdx.x * blockDim.x + threadIdx.x;
    if (g >= TT * HH) return;
    int t = g / HH, h = g - t * HH;
    float* p = x + (size_t)t * DD + h * DKK;
    float s = 0.f;
#pragma unroll
    for (int i = 0; i < DKK; i++) s += p[i] * p[i];
    float sc = rsqrtf(s + EPSF);
#pragma unroll
    for (int i = 0; i < DKK; i++) p[i] *= sc;
}

__global__ void headnorm_k(const float* __restrict__ o, const float* __restrict__ w,
                           __nv_bfloat16* __restrict__ ohi, __nv_bfloat16* __restrict__ olo) {
    int g = blockIdx.x * blockDim.x + threadIdx.x;
    if (g >= TT * HH) return;
    int t = g / HH, h = g - t * HH;
    const float* p = o + (size_t)t * DD + h * DKK;
    float s = 0.f;
#pragma unroll
    for (int i = 0; i < DKK; i++) s += p[i] * p[i];
    float sc = rsqrtf(s / (float)DKK + EPSF);
#pragma unroll
    for (int i = 0; i < DKK; i++) {
        float v = p[i] * sc * w[i];
        __nv_bfloat16 hi, lo; split2(v, hi, lo);
        size_t idx = (size_t)t * DD + h * DKK + i;
        ohi[idx] = hi; olo[idx] = lo;
    }
}

// delta-rule: one block per head, 64 threads (R4-proven version)
__global__ void delta_k(const float* __restrict__ q, const float* __restrict__ k,
                        const float* __restrict__ v, const float* __restrict__ beta,
                        float* __restrict__ o) {
    const int h = blockIdx.x;
    const int j = threadIdx.x;
    float S[DKK];
#pragma unroll
    for (int i = 0; i < DKK; i++) S[i] = 0.f;
    __shared__ float qs[DKK], ks[DKK], vs[DKK];
    __shared__ float bsh;

    int base = h * DKK + j;
    float qn = q[base], kn = k[base], vn = v[base];
    float bn_ = beta[h];

    for (int t = 0; t < TT; t++) {
        qs[j] = qn; ks[j] = kn; vs[j] = vn;
        if (j == 0) bsh = bn_;
        __syncthreads();
        if (t + 1 < TT) {
            int nb = (t + 1) * DD + h * DKK + j;
            qn = q[nb]; kn = k[nb]; vn = v[nb];
            bn_ = beta[(t + 1) * HH + h];
        }
        float a0 = 0.f, a1 = 0.f, a2 = 0.f, a3 = 0.f;
#pragma unroll
        for (int i = 0; i < DKK; i += 4) {
            a0 += ks[i + 0] * S[i + 0];
            a1 += ks[i + 1] * S[i + 1];
            a2 += ks[i + 2] * S[i + 2];
            a3 += ks[i + 3] * S[i + 3];
        }
        float w = bsh * (vs[j] - ((a0 + a1) + (a2 + a3)));
        float o0 = 0.f, o1 = 0.f, o2 = 0.f, o3 = 0.f;
#pragma unroll
        for (int i = 0; i < DKK; i += 4) {
            S[i + 0] += ks[i + 0] * w; o0 += qs[i + 0] * S[i + 0];
            S[i + 1] += ks[i + 1] * w; o1 += qs[i + 1] * S[i + 1];
            S[i + 2] += ks[i + 2] * w; o2 += qs[i + 2] * S[i + 2];
            S[i + 3] += ks[i + 3] * w; o3 += qs[i + 3] * S[i + 3];
        }
        o[t * DD + h * DKK + j] = (o0 + o1) + (o2 + o3);
        __syncthreads();
    }
}

__global__ void silu_mul_k(const float* __restrict__ g, const float* __restrict__ u,
                           __nv_bfloat16* __restrict__ ghi, __nv_bfloat16* __restrict__ glo) {
    int i = blockIdx.x * 256 + threadIdx.x;
    if (i < TT * FFD) {
        float x = g[i];
        float r = (x / (1.f + expf(-x))) * u[i];
        __nv_bfloat16 hi, lo; split2(r, hi, lo);
        ghi[i] = hi; glo[i] = lo;
    }
}

__global__ void loss_rows_k(const float* __restrict__ logits, const int* __restrict__ tgt,
                            float* __restrict__ rowloss) {
    int t = blockIdx.x;
    const float* row = logits + (size_t)t * VV;
    __shared__ float red[256];
    float m = -1e30f;
    for (int i = threadIdx.x; i < VV; i += 256) m = fmaxf(m, row[i]);
    red[threadIdx.x] = m; __syncthreads();
    for (int off = 128; off > 0; off >>= 1) {
        if (threadIdx.x < off) red[threadIdx.x] = fmaxf(red[threadIdx.x], red[threadIdx.x + off]);
        __syncthreads();
    }
    m = red[0]; __syncthreads();
    float s = 0.f;
    for (int i = threadIdx.x; i < VV; i += 256) s += expf(row[i] - m);
    red[threadIdx.x] = s; __syncthreads();
    for (int off = 128; off > 0; off >>= 1) {
        if (threadIdx.x < off) red[threadIdx.x] += red[threadIdx.x + off];
        __syncthreads();
    }
    if (threadIdx.x == 0) {
        int tg = tgt[t];
        if (tg < 0) tg = 0;
        if (tg > VV - 1) tg = VV - 1;
        rowloss[t] = (m + logf(red[0])) - row[tg];
    }
}

__global__ void loss_final_k(const float* __restrict__ rowloss, float* __restrict__ out) {
    __shared__ float red[256];
    float s = 0.f;
    for (int i = threadIdx.x; i < TT; i += 256) s += rowloss[i];
    red[threadIdx.x] = s; __syncthreads();
    for (int off = 128; off > 0; off >>= 1) {
        if (threadIdx.x < off) red[threadIdx.x] += red[threadIdx.x + off];
        __syncthreads();
    }
    if (threadIdx.x == 0) out[0] = red[0] / (float)TT;
}

// ---------------- host launch ----------------

extern "C" void kernel_launch(void* const* d_in, const int* in_sizes, int n_in,
                              void* d_out, int out_size) {
    const int*   idx          = (const int*)d_in[0];
    const int*   targets      = (const int*)d_in[1];
    const float* embed        = (const float*)d_in[2];
    const float* Wq           = (const float*)d_in[3];
    const float* Wk           = (const float*)d_in[4];
    const float* Wv           = (const float*)d_in[5];
    const float* conv_q       = (const float*)d_in[6];
    const float* conv_k       = (const float*)d_in[7];
    const float* conv_v       = (const float*)d_in[8];
    const float* Wb           = (const float*)d_in[9];
    const float* o_norm_w     = (const float*)d_in[10];
    const float* Wo           = (const float*)d_in[11];
    const float* attn_norm_w  = (const float*)d_in[12];
    const float* mlp_norm_w   = (const float*)d_in[13];
    const float* Wgate        = (const float*)d_in[14];
    const float* Wup          = (const float*)d_in[15];
    const float* Wdown        = (const float*)d_in[16];
    const float* final_norm_w = (const float*)d_in[17];
    const float* lm_head      = (const float*)d_in[18];
    float* out = (float*)d_out;

    float *h, *x, *q, *k, *v, *qc, *kc, *vc, *o, *bet, *gate, *up, *rowloss;
    cudaGetSymbolAddress((void**)&h,   g_h);
    cudaGetSymbolAddress((void**)&x,   g_x);
    cudaGetSymbolAddress((void**)&q,   g_q);
    cudaGetSymbolAddress((void**)&k,   g_k);
    cudaGetSymbolAddress((void**)&v,   g_v);
    cudaGetSymbolAddress((void**)&qc,  g_qc);
    cudaGetSymbolAddress((void**)&kc,  g_kc);
    cudaGetSymbolAddress((void**)&vc,  g_vc);
    cudaGetSymbolAddress((void**)&o,   g_o);
    cudaGetSymbolAddress((void**)&bet, g_beta);
    cudaGetSymbolAddress((void**)&gate,g_gate);
    cudaGetSymbolAddress((void**)&up,  g_up);
    cudaGetSymbolAddress((void**)&rowloss, g_rowloss);

    __nv_bfloat16 *whi, *wlo, *xhi, *xlo, *ohi, *olo, *ghi, *glo;
    cudaGetSymbolAddress((void**)&whi, g_whi);
    cudaGetSymbolAddress((void**)&wlo, g_wlo);
    cudaGetSymbolAddress((void**)&xhi, g_xhi);
    cudaGetSymbolAddress((void**)&xlo, g_xlo);
    cudaGetSymbolAddress((void**)&ohi, g_ohi);
    cudaGetSymbolAddress((void**)&olo, g_olo);
    cudaGetSymbolAddress((void**)&ghi, g_ghi);
    cudaGetSymbolAddress((void**)&glo, g_glo);

    cudaFuncSetAttribute(gemm_bf<false>, cudaFuncAttributeMaxDynamicSharedMemorySize, SMEM_GEMM);
    cudaFuncSetAttribute(gemm_bf<true>,  cudaFuncAttributeMaxDynamicSharedMemorySize, SMEM_GEMM);

    // --- pre-convert all weights to bf16 hi/lo planes ([K,N] layout) ---
    {
        struct { const float* src; size_t off; int n; } segs[8] = {
            {Wq,     OFF_WQ, LL * W4},
            {Wk,     OFF_WK, LL * W4},
            {Wv,     OFF_WV, LL * W4},
            {Wo,     OFF_WO, LL * W4},
            {Wgate,  OFF_WG, LL * WFF},
            {Wup,    OFF_WU, LL * WFF},
            {Wdown,  OFF_WD, LL * WFF},
            {lm_head,OFF_LM, DD * VV},
        };
        for (int s = 0; s < 8; s++) {
            int n4 = segs[s].n / 4;
            cvt_k<<<(n4 + 255) / 256, 256>>>(segs[s].src, whi + segs[s].off, wlo + segs[s].off, n4);
        }
    }

    const int eltTD = (TT * DD + 255) / 256;
    const int eltTH = (TT * HH + 255) / 256;
    const int eltTF = (TT * FFD + 255) / 256;

    embed_k<<<eltTD, 256>>>(idx, embed, h);

    dim3 g_qkv(TT / 128, DD / 128, 3);
    dim3 g_one(TT / 128, DD / 128, 1);
    dim3 g_gu (TT / 128, FFD / 128, 2);
    dim3 g_vcb(TT / 128, VV / 128, 1);
    dim3 g_conv(eltTD, 3);
    dim3 g_l2(eltTH, 2);

    for (int l = 0; l < LL; l++) {
        rmsnorm_k<<<TT, 256>>>(h, attn_norm_w + (size_t)l * DD, x, xhi, xlo);

        gemm_bf<false><<<g_qkv, 256, SMEM_GEMM>>>(xhi, xlo,
            whi + OFF_WQ + (size_t)l * W4, whi + OFF_WK + (size_t)l * W4, whi + OFF_WV + (size_t)l * W4,
            wlo + OFF_WQ + (size_t)l * W4, wlo + OFF_WK + (size_t)l * W4, wlo + OFF_WV + (size_t)l * W4,
            q, k, v, TT, DD, DD);
        beta_k<<<(TT * HH + 7) / 8, 256>>>(x, Wb + (size_t)l * DD * HH, bet);

        conv_silu_k<<<g_conv, 256>>>(q, k, v,
            conv_q + (size_t)l * DD * KC, conv_k + (size_t)l * DD * KC, conv_v + (size_t)l * DD * KC,
            qc, kc, vc);
        l2norm_k<<<g_l2, 256>>>(qc, kc);

        delta_k<<<HH, DKK>>>(qc, kc, vc, bet, o);
        headnorm_k<<<eltTH, 256>>>(o, o_norm_w + (size_t)l * DKK, ohi, olo);

        gemm_bf<true><<<g_one, 256, SMEM_GEMM>>>(ohi, olo,
            whi + OFF_WO + (size_t)l * W4, nullptr, nullptr,
            wlo + OFF_WO + (size_t)l * W4, nullptr, nullptr,
            h, nullptr, nullptr, TT, DD, DD);

        rmsnorm_k<<<TT, 256>>>(h, mlp_norm_w + (size_t)l * DD, x, xhi, xlo);
        gemm_bf<false><<<g_gu, 256, SMEM_GEMM>>>(xhi, xlo,
            whi + OFF_WG + (size_t)l * WFF, whi + OFF_WU + (size_t)l * WFF, nullptr,
            wlo + OFF_WG + (size_t)l * WFF, wlo + OFF_WU + (size_t)l * WFF, nullptr,
            gate, up, nullptr, TT, FFD, DD);
        silu_mul_k<<<eltTF, 256>>>(gate, up, ghi, glo);
        gemm_bf<true><<<g_one, 256, SMEM_GEMM>>>(ghi, glo,
            whi + OFF_WD + (size_t)l * WFF, nullptr, nullptr,
            wlo + OFF_WD + (size_t)l * WFF, nullptr, nullptr,
            h, nullptr, nullptr, TT, DD, FFD);
    }

    rmsnorm_k<<<TT, 256>>>(h, final_norm_w, nullptr, xhi, xlo);

    if ((long long)out_size >= (long long)TT * VV) {
        gemm_bf<false><<<g_vcb, 256, SMEM_GEMM>>>(xhi, xlo,
            whi + OFF_LM, nullptr, nullptr,
            wlo + OFF_LM, nullptr, nullptr,
            out, nullptr, nullptr, TT, VV, DD);
        loss_rows_k<<<TT, 256>>>(out, targets, rowloss);
        if ((long long)out_size > (long long)TT * VV)
            loss_final_k<<<1, 256>>>(rowloss, out + (size_t)TT * VV);
    }
}